// round 1
// baseline (speedup 1.0000x reference)
#include <cuda_runtime.h>
#include <cuda_bf16.h>
#include <math.h>

// Problem shapes (fixed by setup_inputs)
#define BB    4
#define TT    4096
#define CC    1024
#define KLEN  1024
#define NFFT  8192
#define LOGN  13
#define FBINS 4097
#define HH    2048
#define MM    (BB*TT)
#define TRANS 16

// ---------------- scratch (device globals; allocation-free) ----------------
__device__ float  g_xn  [(size_t)BB*TT*CC];
__device__ float  g_x2  [(size_t)BB*TT*CC];
__device__ float  g_ffin[(size_t)BB*TT*CC];
__device__ float  g_h   [(size_t)MM*HH];
__device__ float  g_pooled[BB*CC];
__device__ float  g_gctx  [BB*CC];
__device__ float2 g_Fbr [NFFT];
__device__ float2 g_tw  [NFFT/2];

__device__ __forceinline__ float2 cmul(float2 a, float2 b) {
    return make_float2(a.x*b.x - a.y*b.y, a.x*b.y + a.y*b.x);
}

// ---------------- twiddle table: tw[k] = exp(-2*pi*i*k/N) ----------------
__global__ void tw_init_kernel() {
    int k = blockIdx.x * blockDim.x + threadIdx.x;
    if (k < NFFT/2) {
        float sv, cv;
        sincospif(2.0f * (float)k / (float)NFFT, &sv, &cv);
        g_tw[k] = make_float2(cv, -sv);
    }
}

// ---------------- layernorm over channel dim ----------------
__global__ void ln_kernel(const float* __restrict__ x, const float* __restrict__ w,
                          const float* __restrict__ bb, float* __restrict__ out) {
    int row = blockIdx.x;
    const float* xr = x + (size_t)row * CC;
    float* orow = out + (size_t)row * CC;
    float s = 0.f, s2 = 0.f;
    for (int c = threadIdx.x; c < CC; c += blockDim.x) { float v = xr[c]; s += v; s2 += v*v; }
    __shared__ float sh1[8], sh2[8];
    for (int o = 16; o; o >>= 1) { s += __shfl_down_sync(~0u, s, o); s2 += __shfl_down_sync(~0u, s2, o); }
    int wid = threadIdx.x >> 5, lid = threadIdx.x & 31;
    if (!lid) { sh1[wid] = s; sh2[wid] = s2; }
    __syncthreads();
    if (threadIdx.x < 8) {
        s = sh1[threadIdx.x]; s2 = sh2[threadIdx.x];
        for (int o = 4; o; o >>= 1) { s += __shfl_down_sync(0xffu, s, o); s2 += __shfl_down_sync(0xffu, s2, o); }
        if (!threadIdx.x) { sh1[0] = s; sh2[0] = s2; }
    }
    __syncthreads();
    float mean = sh1[0] / CC;
    float var  = sh2[0] / CC - mean*mean;
    float inv  = rsqrtf(var + 1e-5f);
    for (int c = threadIdx.x; c < CC; c += blockDim.x)
        orow[c] = (xr[c] - mean) * inv * w[c] + bb[c];
}

// ---------------- pooled = mean over T of xn ----------------
__global__ void pool_kernel() {
    int c = blockIdx.x * blockDim.x + threadIdx.x;
    int b = blockIdx.y;
    const float* p = g_xn + (size_t)b * TT * CC + c;
    float s = 0.f;
    for (int t = 0; t < TT; t++) s += p[(size_t)t * CC];
    g_pooled[b*CC + c] = s / (float)TT;
}

// ---------------- g_ctx = sigmoid(pooled @ Wc + bc) ----------------
__global__ void gctx_kernel(const float* __restrict__ Wc, const float* __restrict__ bc) {
    int co = blockIdx.x * blockDim.x + threadIdx.x;
    int b  = blockIdx.y;
    float s = bc[co];
    const float* pr = g_pooled + b*CC;
    for (int ci = 0; ci < CC; ci++) s += pr[ci] * Wc[(size_t)ci*CC + co];
    g_gctx[b*CC + co] = 1.f / (1.f + expf(-s));
}

// ---------------- FFT primitives (shared memory, radix-2) ----------------
// Forward DIF: natural in -> bit-reversed out, twiddles exp(-i*...)
__device__ void fft_dif(float2* s, const float2* __restrict__ tw) {
    #pragma unroll 1
    for (int st = LOGN-1; st >= 0; st--) {
        int len = 1 << st;
        for (int j = threadIdx.x; j < NFFT/2; j += blockDim.x) {
            int pos = j & (len - 1);
            int i0  = ((j >> st) << (st + 1)) | pos;
            int i1  = i0 + len;
            float2 a = s[i0], b = s[i1];
            float2 d = make_float2(a.x - b.x, a.y - b.y);
            s[i0] = make_float2(a.x + b.x, a.y + b.y);
            float2 w = tw[pos << (LOGN-1 - st)];
            s[i1] = cmul(d, w);
        }
        __syncthreads();
    }
}
// Inverse DIT: bit-reversed in -> natural out, conj twiddles. (1/N is folded into F.)
__device__ void fft_dit_inv(float2* s, const float2* __restrict__ tw) {
    #pragma unroll 1
    for (int st = 0; st < LOGN; st++) {
        int len = 1 << st;
        for (int j = threadIdx.x; j < NFFT/2; j += blockDim.x) {
            int pos = j & (len - 1);
            int i0  = ((j >> st) << (st + 1)) | pos;
            int i1  = i0 + len;
            float2 w = tw[pos << (LOGN-1 - st)];
            float2 b = s[i1];
            // b * conj(w)
            float2 bw = make_float2(b.x*w.x + b.y*w.y, b.y*w.x - b.x*w.y);
            float2 a = s[i0];
            s[i0] = make_float2(a.x + bw.x, a.y + bw.y);
            s[i1] = make_float2(a.x - bw.x, a.y - bw.y);
        }
        __syncthreads();
    }
}

// ---------------- filter spectrum, gated+masked, bit-reversed, /N folded ----------------
__global__ void __launch_bounds__(512) filt_kernel(const float* __restrict__ kern,
                                                   const float* __restrict__ logits,
                                                   const int* __restrict__ cutoff_p) {
    extern __shared__ float2 sh[];
    float2* s = sh;
    for (int j = threadIdx.x; j < NFFT; j += blockDim.x)
        s[j] = make_float2(j < KLEN ? kern[j] : 0.f, 0.f);
    __syncthreads();
    fft_dif(s, g_tw);
    int cut = *cutoff_p;
    int c = cut < FBINS ? cut : FBINS;
    for (int j = threadIdx.x; j < NFFT; j += blockDim.x) {
        int f  = (int)(__brev((unsigned)j) >> (32 - LOGN));
        int fm = f <= NFFT - f ? f : NFFT - f;           // Hermitian fold; f=0 -> 0
        float gate = 1.f / (1.f + expf(-logits[fm]));
        float m = 1.f;
        if (c < FBINS) {
            int tr = TRANS < c ? TRANS : c;
            if (fm >= c) m = 0.f;
            else if (fm >= c - tr) {
                int i = fm - (c - tr);
                float t = (tr > 1) ? (float)i / (float)(tr - 1) : 0.f;
                m = 0.5f * (1.f + cospif(t));
            }
        }
        float sc = gate * m * (1.f / (float)NFFT);
        g_Fbr[j] = make_float2(s[j].x * sc, s[j].y * sc);
    }
}

// ---------------- main spectral conv: 2 channels per block via complex packing ----------------
__global__ void __launch_bounds__(512) conv_kernel(const float* __restrict__ x,
                                                   const float* __restrict__ gain) {
    extern __shared__ float2 sh[];
    float2* s   = sh;          // NFFT
    float2* tws = sh + NFFT;   // NFFT/2
    int blk = blockIdx.x;
    int b   = blk / (CC/2);
    int c0  = (blk % (CC/2)) * 2;

    for (int k = threadIdx.x; k < NFFT/2; k += blockDim.x) tws[k] = g_tw[k];

    const float2* xrow = (const float2*)(g_xn + (size_t)b*TT*CC + c0);
    for (int t = threadIdx.x; t < NFFT; t += blockDim.x)
        s[t] = (t < TT) ? xrow[(size_t)t * (CC/2)] : make_float2(0.f, 0.f);
    __syncthreads();

    fft_dif(s, tws);                       // ends with syncthreads

    for (int j = threadIdx.x; j < NFFT; j += blockDim.x)
        s[j] = cmul(s[j], g_Fbr[j]);
    __syncthreads();

    fft_dit_inv(s, tws);                   // ends with syncthreads

    float ga = gain[c0]   * g_gctx[b*CC + c0];
    float gb = gain[c0+1] * g_gctx[b*CC + c0+1];
    const float2* rrow = (const float2*)(x   + (size_t)b*TT*CC + c0);
    float2*       orow = (float2*)      (g_x2 + (size_t)b*TT*CC + c0);
    for (int t = threadIdx.x; t < TT; t += blockDim.x) {
        float2 r = rrow[(size_t)t * (CC/2)];
        float2 w = s[t];
        orow[(size_t)t * (CC/2)] = make_float2(r.x + w.x*ga, r.y + w.y*gb);
    }
}

// ---------------- SGEMM 128x128x8, 8x8 micro-tile, fused epilogues ----------------
// EPI=0: out = gelu(acc + bias)        (store to Cout [M x N])
// EPI=1: out = acc + bias + res        (store to Cout [M x N])
template<int EPI>
__global__ void __launch_bounds__(256) gemm_kernel(const float* __restrict__ A,
                                                   const float* __restrict__ Bm,
                                                   const float* __restrict__ bias,
                                                   const float* __restrict__ res,
                                                   float* __restrict__ Cout,
                                                   int Ndim, int Kdim) {
    __shared__ float As[8][128];
    __shared__ float Bs[8][128];
    int bm = blockIdx.y * 128, bn = blockIdx.x * 128;
    int tid = threadIdx.x;
    int arow = tid >> 1;
    int acol = (tid & 1) * 4;
    int brow = tid >> 5;
    int bcol = (tid & 31) * 4;
    int ty = tid >> 4, tx = tid & 15;

    float acc[8][8];
    #pragma unroll
    for (int i = 0; i < 8; i++)
        #pragma unroll
        for (int j = 0; j < 8; j++) acc[i][j] = 0.f;

    for (int k0 = 0; k0 < Kdim; k0 += 8) {
        float4 av = *(const float4*)(A  + (size_t)(bm + arow)*Kdim + k0 + acol);
        float4 bv = *(const float4*)(Bm + (size_t)(k0 + brow)*Ndim + bn + bcol);
        As[acol+0][arow] = av.x; As[acol+1][arow] = av.y;
        As[acol+2][arow] = av.z; As[acol+3][arow] = av.w;
        *(float4*)&Bs[brow][bcol] = bv;
        __syncthreads();
        #pragma unroll
        for (int kk = 0; kk < 8; kk++) {
            float ar[8], br[8];
            *(float4*)(ar)   = *(const float4*)&As[kk][ty*8];
            *(float4*)(ar+4) = *(const float4*)&As[kk][ty*8 + 4];
            *(float4*)(br)   = *(const float4*)&Bs[kk][tx*8];
            *(float4*)(br+4) = *(const float4*)&Bs[kk][tx*8 + 4];
            #pragma unroll
            for (int i = 0; i < 8; i++)
                #pragma unroll
                for (int j = 0; j < 8; j++)
                    acc[i][j] += ar[i] * br[j];
        }
        __syncthreads();
    }

    #pragma unroll
    for (int i = 0; i < 8; i++) {
        int m = bm + ty*8 + i;
        #pragma unroll
        for (int j = 0; j < 8; j++) {
            int n = bn + tx*8 + j;
            float v = acc[i][j] + bias[n];
            if (EPI == 0) {
                v = 0.5f * v * (1.f + erff(v * 0.70710678118654752f));
            } else {
                v += res[(size_t)m * Ndim + n];
            }
            Cout[(size_t)m * Ndim + n] = v;
        }
    }
}

// ---------------- launch ----------------
extern "C" void kernel_launch(void* const* d_in, const int* in_sizes, int n_in,
                              void* d_out, int out_size) {
    const float* x    = (const float*)d_in[0];
    const float* kern = (const float*)d_in[1];
    const float* gain = (const float*)d_in[2];
    const float* gfl  = (const float*)d_in[3];
    const float* gcw  = (const float*)d_in[4];
    const float* gcb  = (const float*)d_in[5];
    const float* lnw  = (const float*)d_in[6];
    const float* lnb  = (const float*)d_in[7];
    const float* flnw = (const float*)d_in[8];
    const float* flnb = (const float*)d_in[9];
    const float* w1   = (const float*)d_in[10];
    const float* b1   = (const float*)d_in[11];
    const float* w2   = (const float*)d_in[12];
    const float* b2   = (const float*)d_in[13];
    const int*   cut  = (const int*)d_in[14];
    float* out = (float*)d_out;

    cudaFuncSetAttribute(filt_kernel, cudaFuncAttributeMaxDynamicSharedMemorySize, NFFT * 8);
    cudaFuncSetAttribute(conv_kernel, cudaFuncAttributeMaxDynamicSharedMemorySize, (NFFT + NFFT/2) * 8);

    float *xn_p = nullptr, *x2_p = nullptr, *ffin_p = nullptr, *h_p = nullptr;
    cudaGetSymbolAddress((void**)&xn_p,   g_xn);
    cudaGetSymbolAddress((void**)&x2_p,   g_x2);
    cudaGetSymbolAddress((void**)&ffin_p, g_ffin);
    cudaGetSymbolAddress((void**)&h_p,    g_h);

    tw_init_kernel<<<(NFFT/2 + 255)/256, 256>>>();
    ln_kernel<<<MM, 256>>>(x, lnw, lnb, xn_p);
    pool_kernel<<<dim3(CC/256, BB), 256>>>();
    gctx_kernel<<<dim3(CC/256, BB), 256>>>(gcw, gcb);
    filt_kernel<<<1, 512, NFFT * 8>>>(kern, gfl, cut);
    conv_kernel<<<BB * (CC/2), 512, (NFFT + NFFT/2) * 8>>>(x, gain);
    ln_kernel<<<MM, 256>>>(x2_p, flnw, flnb, ffin_p);
    gemm_kernel<0><<<dim3(HH/128, MM/128), 256>>>(ffin_p, w1, b1, nullptr, h_p, HH, CC);
    gemm_kernel<1><<<dim3(CC/128, MM/128), 256>>>(h_p, w2, b2, x2_p, out, CC, HH);
}

// round 2
// speedup vs baseline: 1.0018x; 1.0018x over previous
#include <cuda_runtime.h>
#include <cuda_bf16.h>
#include <math.h>

// Problem shapes (fixed by setup_inputs)
#define BB    4
#define TT    4096
#define CC    1024
#define KLEN  1024
#define NFFT  8192
#define LOGN  13
#define FBINS 4097
#define HH    2048
#define MM    (BB*TT)
#define TRANS 16

// ---------------- scratch (device globals; allocation-free) ----------------
__device__ float  g_xn  [(size_t)BB*TT*CC];
__device__ float  g_x2  [(size_t)BB*TT*CC];
__device__ float  g_ffin[(size_t)BB*TT*CC];
__device__ float  g_h   [(size_t)MM*HH];
__device__ float  g_pooled[BB*CC];
__device__ float  g_gctx  [BB*CC];
__device__ float2 g_Fbr [NFFT];
__device__ float2 g_tw  [NFFT/2];

__device__ __forceinline__ float2 cmul(float2 a, float2 b) {
    return make_float2(a.x*b.x - a.y*b.y, a.x*b.y + a.y*b.x);
}

// ---------------- twiddle table: tw[k] = exp(-2*pi*i*k/N) ----------------
__global__ void tw_init_kernel() {
    int k = blockIdx.x * blockDim.x + threadIdx.x;
    if (k < NFFT/2) {
        float sv, cv;
        sincospif(2.0f * (float)k / (float)NFFT, &sv, &cv);
        g_tw[k] = make_float2(cv, -sv);
    }
}

// ---------------- layernorm over channel dim ----------------
__global__ void ln_kernel(const float* __restrict__ x, const float* __restrict__ w,
                          const float* __restrict__ bb, float* __restrict__ out) {
    int row = blockIdx.x;
    const float* xr = x + (size_t)row * CC;
    float* orow = out + (size_t)row * CC;
    float s = 0.f, s2 = 0.f;
    for (int c = threadIdx.x; c < CC; c += blockDim.x) { float v = xr[c]; s += v; s2 += v*v; }
    __shared__ float sh1[8], sh2[8];
    for (int o = 16; o; o >>= 1) { s += __shfl_down_sync(~0u, s, o); s2 += __shfl_down_sync(~0u, s2, o); }
    int wid = threadIdx.x >> 5, lid = threadIdx.x & 31;
    if (!lid) { sh1[wid] = s; sh2[wid] = s2; }
    __syncthreads();
    if (threadIdx.x < 8) {
        s = sh1[threadIdx.x]; s2 = sh2[threadIdx.x];
        for (int o = 4; o; o >>= 1) { s += __shfl_down_sync(0xffu, s, o); s2 += __shfl_down_sync(0xffu, s2, o); }
        if (!threadIdx.x) { sh1[0] = s; sh2[0] = s2; }
    }
    __syncthreads();
    float mean = sh1[0] / CC;
    float var  = sh2[0] / CC - mean*mean;
    float inv  = rsqrtf(var + 1e-5f);
    for (int c = threadIdx.x; c < CC; c += blockDim.x)
        orow[c] = (xr[c] - mean) * inv * w[c] + bb[c];
}

// ---------------- pooled = mean over T of xn ----------------
__global__ void pool_kernel() {
    int c = blockIdx.x * blockDim.x + threadIdx.x;
    int b = blockIdx.y;
    const float* p = g_xn + (size_t)b * TT * CC + c;
    float s = 0.f;
    for (int t = 0; t < TT; t++) s += p[(size_t)t * CC];
    g_pooled[b*CC + c] = s / (float)TT;
}

// ---------------- g_ctx = sigmoid(pooled @ Wc + bc) ----------------
__global__ void gctx_kernel(const float* __restrict__ Wc, const float* __restrict__ bc) {
    int co = blockIdx.x * blockDim.x + threadIdx.x;
    int b  = blockIdx.y;
    float s = bc[co];
    const float* pr = g_pooled + b*CC;
    for (int ci = 0; ci < CC; ci++) s += pr[ci] * Wc[(size_t)ci*CC + co];
    g_gctx[b*CC + co] = 1.f / (1.f + expf(-s));
}

// ---------------- FFT primitives (shared memory, radix-2) ----------------
// Forward DIF: natural in -> bit-reversed out, twiddles exp(-i*...)
__device__ void fft_dif(float2* s, const float2* __restrict__ tw) {
    #pragma unroll 1
    for (int st = LOGN-1; st >= 0; st--) {
        int len = 1 << st;
        for (int j = threadIdx.x; j < NFFT/2; j += blockDim.x) {
            int pos = j & (len - 1);
            int i0  = ((j >> st) << (st + 1)) | pos;
            int i1  = i0 + len;
            float2 a = s[i0], b = s[i1];
            float2 d = make_float2(a.x - b.x, a.y - b.y);
            s[i0] = make_float2(a.x + b.x, a.y + b.y);
            float2 w = tw[pos << (LOGN-1 - st)];
            s[i1] = cmul(d, w);
        }
        __syncthreads();
    }
}
// Inverse DIT: bit-reversed in -> natural out, conj twiddles. (1/N is folded into F.)
__device__ void fft_dit_inv(float2* s, const float2* __restrict__ tw) {
    #pragma unroll 1
    for (int st = 0; st < LOGN; st++) {
        int len = 1 << st;
        for (int j = threadIdx.x; j < NFFT/2; j += blockDim.x) {
            int pos = j & (len - 1);
            int i0  = ((j >> st) << (st + 1)) | pos;
            int i1  = i0 + len;
            float2 w = tw[pos << (LOGN-1 - st)];
            float2 b = s[i1];
            // b * conj(w)
            float2 bw = make_float2(b.x*w.x + b.y*w.y, b.y*w.x - b.x*w.y);
            float2 a = s[i0];
            s[i0] = make_float2(a.x + bw.x, a.y + bw.y);
            s[i1] = make_float2(a.x - bw.x, a.y - bw.y);
        }
        __syncthreads();
    }
}

// ---------------- filter spectrum, gated+masked, bit-reversed, /N folded ----------------
__global__ void __launch_bounds__(512) filt_kernel(const float* __restrict__ kern,
                                                   const float* __restrict__ logits,
                                                   const int* __restrict__ cutoff_p) {
    extern __shared__ float2 sh[];
    float2* s = sh;
    for (int j = threadIdx.x; j < NFFT; j += blockDim.x)
        s[j] = make_float2(j < KLEN ? kern[j] : 0.f, 0.f);
    __syncthreads();
    fft_dif(s, g_tw);
    int cut = *cutoff_p;
    int c = cut < FBINS ? cut : FBINS;
    for (int j = threadIdx.x; j < NFFT; j += blockDim.x) {
        int f  = (int)(__brev((unsigned)j) >> (32 - LOGN));
        int fm = f <= NFFT - f ? f : NFFT - f;           // Hermitian fold; f=0 -> 0
        float gate = 1.f / (1.f + expf(-logits[fm]));
        float m = 1.f;
        if (c < FBINS) {
            int tr = TRANS < c ? TRANS : c;
            if (fm >= c) m = 0.f;
            else if (fm >= c - tr) {
                int i = fm - (c - tr);
                float t = (tr > 1) ? (float)i / (float)(tr - 1) : 0.f;
                m = 0.5f * (1.f + cospif(t));
            }
        }
        float sc = gate * m * (1.f / (float)NFFT);
        g_Fbr[j] = make_float2(s[j].x * sc, s[j].y * sc);
    }
}

// ---------------- main spectral conv: 2 channels per block via complex packing ----------------
__global__ void __launch_bounds__(512) conv_kernel(const float* __restrict__ x,
                                                   const float* __restrict__ gain) {
    extern __shared__ float2 sh[];
    float2* s   = sh;          // NFFT
    float2* tws = sh + NFFT;   // NFFT/2
    int blk = blockIdx.x;
    int b   = blk / (CC/2);
    int c0  = (blk % (CC/2)) * 2;

    for (int k = threadIdx.x; k < NFFT/2; k += blockDim.x) tws[k] = g_tw[k];

    const float2* xrow = (const float2*)(g_xn + (size_t)b*TT*CC + c0);
    for (int t = threadIdx.x; t < NFFT; t += blockDim.x)
        s[t] = (t < TT) ? xrow[(size_t)t * (CC/2)] : make_float2(0.f, 0.f);
    __syncthreads();

    fft_dif(s, tws);                       // ends with syncthreads

    for (int j = threadIdx.x; j < NFFT; j += blockDim.x)
        s[j] = cmul(s[j], g_Fbr[j]);
    __syncthreads();

    fft_dit_inv(s, tws);                   // ends with syncthreads

    float ga = gain[c0]   * g_gctx[b*CC + c0];
    float gb = gain[c0+1] * g_gctx[b*CC + c0+1];
    const float2* rrow = (const float2*)(x   + (size_t)b*TT*CC + c0);
    float2*       orow = (float2*)      (g_x2 + (size_t)b*TT*CC + c0);
    for (int t = threadIdx.x; t < TT; t += blockDim.x) {
        float2 r = rrow[(size_t)t * (CC/2)];
        float2 w = s[t];
        orow[(size_t)t * (CC/2)] = make_float2(r.x + w.x*ga, r.y + w.y*gb);
    }
}

// ---------------- SGEMM 128x128x8, 8x8 micro-tile, fused epilogues ----------------
// EPI=0: out = gelu(acc + bias)        (store to Cout [M x N])
// EPI=1: out = acc + bias + res        (store to Cout [M x N])
template<int EPI>
__global__ void __launch_bounds__(256) gemm_kernel(const float* __restrict__ A,
                                                   const float* __restrict__ Bm,
                                                   const float* __restrict__ bias,
                                                   const float* __restrict__ res,
                                                   float* __restrict__ Cout,
                                                   int Ndim, int Kdim) {
    __shared__ float As[8][128];
    __shared__ float Bs[8][128];
    int bm = blockIdx.y * 128, bn = blockIdx.x * 128;
    int tid = threadIdx.x;
    int arow = tid >> 1;
    int acol = (tid & 1) * 4;
    int brow = tid >> 5;
    int bcol = (tid & 31) * 4;
    int ty = tid >> 4, tx = tid & 15;

    float acc[8][8];
    #pragma unroll
    for (int i = 0; i < 8; i++)
        #pragma unroll
        for (int j = 0; j < 8; j++) acc[i][j] = 0.f;

    for (int k0 = 0; k0 < Kdim; k0 += 8) {
        float4 av = *(const float4*)(A  + (size_t)(bm + arow)*Kdim + k0 + acol);
        float4 bv = *(const float4*)(Bm + (size_t)(k0 + brow)*Ndim + bn + bcol);
        As[acol+0][arow] = av.x; As[acol+1][arow] = av.y;
        As[acol+2][arow] = av.z; As[acol+3][arow] = av.w;
        *(float4*)&Bs[brow][bcol] = bv;
        __syncthreads();
        #pragma unroll
        for (int kk = 0; kk < 8; kk++) {
            float ar[8], br[8];
            *(float4*)(ar)   = *(const float4*)&As[kk][ty*8];
            *(float4*)(ar+4) = *(const float4*)&As[kk][ty*8 + 4];
            *(float4*)(br)   = *(const float4*)&Bs[kk][tx*8];
            *(float4*)(br+4) = *(const float4*)&Bs[kk][tx*8 + 4];
            #pragma unroll
            for (int i = 0; i < 8; i++)
                #pragma unroll
                for (int j = 0; j < 8; j++)
                    acc[i][j] += ar[i] * br[j];
        }
        __syncthreads();
    }

    #pragma unroll
    for (int i = 0; i < 8; i++) {
        int m = bm + ty*8 + i;
        #pragma unroll
        for (int j = 0; j < 8; j++) {
            int n = bn + tx*8 + j;
            float v = acc[i][j] + bias[n];
            if (EPI == 0) {
                v = 0.5f * v * (1.f + erff(v * 0.70710678118654752f));
            } else {
                v += res[(size_t)m * Ndim + n];
            }
            Cout[(size_t)m * Ndim + n] = v;
        }
    }
}

// ---------------- launch ----------------
extern "C" void kernel_launch(void* const* d_in, const int* in_sizes, int n_in,
                              void* d_out, int out_size) {
    const float* x    = (const float*)d_in[0];
    const float* kern = (const float*)d_in[1];
    const float* gain = (const float*)d_in[2];
    const float* gfl  = (const float*)d_in[3];
    const float* gcw  = (const float*)d_in[4];
    const float* gcb  = (const float*)d_in[5];
    const float* lnw  = (const float*)d_in[6];
    const float* lnb  = (const float*)d_in[7];
    const float* flnw = (const float*)d_in[8];
    const float* flnb = (const float*)d_in[9];
    const float* w1   = (const float*)d_in[10];
    const float* b1   = (const float*)d_in[11];
    const float* w2   = (const float*)d_in[12];
    const float* b2   = (const float*)d_in[13];
    const int*   cut  = (const int*)d_in[14];
    float* out = (float*)d_out;

    cudaFuncSetAttribute(filt_kernel, cudaFuncAttributeMaxDynamicSharedMemorySize, NFFT * 8);
    cudaFuncSetAttribute(conv_kernel, cudaFuncAttributeMaxDynamicSharedMemorySize, (NFFT + NFFT/2) * 8);

    float *xn_p = nullptr, *x2_p = nullptr, *ffin_p = nullptr, *h_p = nullptr;
    cudaGetSymbolAddress((void**)&xn_p,   g_xn);
    cudaGetSymbolAddress((void**)&x2_p,   g_x2);
    cudaGetSymbolAddress((void**)&ffin_p, g_ffin);
    cudaGetSymbolAddress((void**)&h_p,    g_h);

    tw_init_kernel<<<(NFFT/2 + 255)/256, 256>>>();
    ln_kernel<<<MM, 256>>>(x, lnw, lnb, xn_p);
    pool_kernel<<<dim3(CC/256, BB), 256>>>();
    gctx_kernel<<<dim3(CC/256, BB), 256>>>(gcw, gcb);
    filt_kernel<<<1, 512, NFFT * 8>>>(kern, gfl, cut);
    conv_kernel<<<BB * (CC/2), 512, (NFFT + NFFT/2) * 8>>>(x, gain);
    ln_kernel<<<MM, 256>>>(x2_p, flnw, flnb, ffin_p);
    gemm_kernel<0><<<dim3(HH/128, MM/128), 256>>>(ffin_p, w1, b1, nullptr, h_p, HH, CC);
    gemm_kernel<1><<<dim3(CC/128, MM/128), 256>>>(h_p, w2, b2, x2_p, out, CC, HH);
}